// round 17
// baseline (speedup 1.0000x reference)
#include <cuda_runtime.h>
#include <math.h>
#include <stdint.h>

#define BATCH    8
#define CH       128
#define T_AUDIO  16384
#define COND_CH  80
#define T_MEL    32
#define N_LAYERS 4
#define KPL      (CH*CH*3)        /* 49152 */
#define KC       (KPL*N_LAYERS)   /* 196608 */
#define BC       (CH*N_LAYERS)    /* 512 */

#define NT       128              /* output chunk */
#define TILES    (T_AUDIO/NT)     /* 128 */
#define NCTAS    148              /* flattened persistent grid */
#define WFULL    24576            /* per (b,l): 192 frag-rows x 32 lanes x 4 words */
#define BUFW     160              /* compute grid width (chunk + 2*16 halo) */
#define YSTR     168              /* yf32 stride: 168%32==8 -> conflict-free 64b phases */
#define XBW      184              /* xbf stride: 184%32==24 -> B frags conflict-free */
#define WSTR     68               /* padded w2-slice row stride (68%32==4 -> LDS.128 ok) */

// ---------------- device scratch ----------------
__device__ float    g_h0[BATCH*64*T_MEL];
__device__ float    g_hmean[BATCH*64];
__device__ uint32_t g_Wh[BATCH*N_LAYERS*WFULL];
__device__ float    g_bias[BATCH*N_LAYERS*CH];

__device__ __forceinline__ float gelu_exact(float x) {
    return 0.5f * x * (1.0f + erff(x * 0.7071067811865475f));
}
__device__ __forceinline__ uint32_t pack_bf16x2(float lo, float hi) {
    uint32_t u;
    asm("cvt.rn.bf16x2.f32 %0, %1, %2;" : "=r"(u) : "f"(hi), "f"(lo));
    return u;
}
__device__ __forceinline__ uint32_t smem_u32(const void* p) {
    uint32_t a;
    asm("{ .reg .u64 t; cvta.to.shared.u64 t, %1; cvt.u32.u64 %0, t; }" : "=r"(a) : "l"(p));
    return a;
}
__device__ __forceinline__ void cp16(uint32_t dst, const void* src) {
    asm volatile("cp.async.cg.shared.global [%0], [%1], 16;" :: "r"(dst), "l"(src));
}
#define CP_COMMIT() asm volatile("cp.async.commit_group;" ::: "memory")
#define CP_WAIT0()  asm volatile("cp.async.wait_group 0;" ::: "memory")

#define MMA16(d_, a_, b_) \
  asm volatile("mma.sync.aligned.m16n8k16.row.col.f32.bf16.bf16.f32 " \
    "{%0,%1,%2,%3}, {%4,%5,%6,%7}, {%8,%9}, {%0,%1,%2,%3};" \
    : "+f"((d_)[0]), "+f"((d_)[1]), "+f"((d_)[2]), "+f"((d_)[3]) \
    : "r"((a_)[0]), "r"((a_)[1]), "r"((a_)[2]), "r"((a_)[3]), \
      "r"((b_)[0]), "r"((b_)[1]))

// =========================================================================
// Condnet C1: layer 0 (conv5, pad2, gelu). Grid (8 g, 8 b), 256 threads.
// =========================================================================
__global__ void __launch_bounds__(256)
cond_l0_kernel(const float* __restrict__ cond,
               const float* __restrict__ w0, const float* __restrict__ b0) {
    __shared__ float scp[COND_CH*36];     // padded: col = t+2
    __shared__ float sw[8*400];           // [ch][i*5+k] linear

    const int g = blockIdx.x;
    const int b = blockIdx.y;
    const int tid = threadIdx.x;
    const int wid = tid >> 5;
    const int lane = tid & 31;

    for (int idx = tid; idx < COND_CH*36; idx += 256) {
        const int row = idx / 36;
        const int t   = (idx - row*36) - 2;
        scp[idx] = (t >= 0 && t < T_MEL) ? cond[(b*COND_CH + row)*T_MEL + t] : 0.0f;
    }
    for (int idx = tid; idx < 8*400; idx += 256)
        sw[idx] = w0[g*8*400 + idx];
    __syncthreads();

    const float* wr = sw + wid*400;
    float acc = b0[g*8 + wid];
    #pragma unroll 4
    for (int i = 0; i < COND_CH; ++i) {
        const float4 w4 = *(const float4*)&wr[i*5];
        const float  w5 = wr[i*5 + 4];
        const float* xr = scp + i*36 + lane;
        acc += w4.x*xr[0] + w4.y*xr[1] + w4.z*xr[2] + w4.w*xr[3] + w5*xr[4];
    }
    g_h0[(b*64 + g*8 + wid)*T_MEL + lane] = gelu_exact(acc);
}

// =========================================================================
// Condnet C2: layer 1 (conv3, pad1, gelu) + mean over t. Grid 8, 1024 thr.
// =========================================================================
__global__ void __launch_bounds__(1024)
cond_l1_kernel(const float* __restrict__ w1, const float* __restrict__ b1) {
    extern __shared__ float smemf[];
    float* shp = smemf;             // [64][34] padded: col = t+1
    float* sw1 = smemf + 64*34;     // [64][192] linear

    const int b = blockIdx.x;
    const int tid = threadIdx.x;
    const int wid = tid >> 5;
    const int lane = tid & 31;

    for (int idx = tid; idx < 64*34; idx += 1024) {
        const int row = idx / 34;
        const int t   = (idx - row*34) - 1;
        shp[idx] = (t >= 0 && t < T_MEL) ? g_h0[(b*64 + row)*T_MEL + t] : 0.0f;
    }
    for (int idx = tid; idx < 64*192; idx += 1024)
        sw1[idx] = w1[idx];
    __syncthreads();

    const int o0 = wid*2, o1 = wid*2 + 1;
    const float* wr0 = sw1 + o0*192;
    const float* wr1 = sw1 + o1*192;
    float a0 = b1[o0], a1 = b1[o1];
    #pragma unroll 4
    for (int i = 0; i < 64; ++i) {
        const float* xr = shp + i*34 + lane;
        const float x0 = xr[0], x1 = xr[1], x2 = xr[2];
        const float2 wa = *(const float2*)&wr0[i*3];
        const float  wb = wr0[i*3 + 2];
        const float2 wc = *(const float2*)&wr1[i*3];
        const float  wd = wr1[i*3 + 2];
        a0 += wa.x*x0 + wa.y*x1 + wb*x2;
        a1 += wc.x*x0 + wc.y*x1 + wd*x2;
    }
    float v0 = gelu_exact(a0);
    float v1 = gelu_exact(a1);
    #pragma unroll
    for (int off = 16; off; off >>= 1) {
        v0 += __shfl_xor_sync(0xffffffffu, v0, off);
        v1 += __shfl_xor_sync(0xffffffffu, v1, off);
    }
    if (lane == 0) {
        g_hmean[b*64 + o0] = v0 * (1.0f/T_MEL);
        g_hmean[b*64 + o1] = v1 * (1.0f/T_MEL);
    }
}

// =========================================================================
// Kernel B v2: LVC weights, COALESCED. Block (l,co) stages the 384
// contiguous w2 rows of one output channel into smem (linear float4,
// padded stride 68), one thread per row computes the 8 batch dots,
// then 192 threads pack bf16x2 pairs via the inverse fragment mapping.
// Writes are 4B scattered but g_Wh (3MB) is L2-resident. Blocks 512+
// handle the 512 bias rows (tiny, old path).
// =========================================================================
#define SMEM_W ((384*WSTR + 512 + 384*8) * 4)   /* 118784 B */

__global__ void __launch_bounds__(384)
weights_kernel(const float* __restrict__ w2, const float* __restrict__ b2) {
    extern __shared__ float smw[];
    float* sw2 = smw;                 // [384][WSTR]
    float* sh  = smw + 384*WSTR;      // [8][64]
    float* sv  = sh + 512;            // [384][8]

    const int tid = threadIdx.x;

    for (int i = tid; i < BATCH*64; i += 384) sh[i] = g_hmean[i];

    if (blockIdx.x >= 512) {          // ---- bias rows ----
        __syncthreads();
        const int idx = (blockIdx.x - 512)*384 + tid;
        if (idx < BC) {
            const size_t c = (size_t)KC + idx;
            float acc[BATCH];
            #pragma unroll
            for (int b = 0; b < BATCH; ++b) acc[b] = 0.0f;
            const float4* wr = (const float4*)(w2 + c*64);
            #pragma unroll 4
            for (int q = 0; q < 16; ++q) {
                float4 w = wr[q];
                #pragma unroll
                for (int b = 0; b < BATCH; ++b) {
                    const float* h = sh + b*64 + q*4;
                    acc[b] += w.x*h[0] + w.y*h[1] + w.z*h[2] + w.w*h[3];
                }
            }
            const float bias = b2[c];
            #pragma unroll
            for (int b = 0; b < BATCH; ++b)
                g_bias[b*N_LAYERS*CH + idx] = acc[b] + bias;
        }
        return;
    }

    const int l  = blockIdx.x >> 7;
    const int co = blockIdx.x & 127;
    const size_t row_base = (size_t)l*KPL + (size_t)co*384;

    // coalesced slice load: 384 rows x 64 floats
    {
        const float4* src = (const float4*)(w2 + row_base*64);
        #pragma unroll 4
        for (int i = tid; i < 384*16; i += 384) {
            const int r = i >> 4, q = i & 15;
            *(float4*)&sw2[r*WSTR + q*4] = src[i];
        }
    }
    __syncthreads();

    // one thread per row: 8 batch dots + bias
    {
        const int r = tid;
        float acc[BATCH];
        #pragma unroll
        for (int b = 0; b < BATCH; ++b) acc[b] = 0.0f;
        #pragma unroll 4
        for (int q = 0; q < 16; ++q) {
            const float4 w = *(const float4*)&sw2[r*WSTR + q*4];
            #pragma unroll
            for (int b = 0; b < BATCH; ++b) {
                const float* h = sh + b*64 + q*4;
                acc[b] += w.x*h[0] + w.y*h[1] + w.z*h[2] + w.w*h[3];
            }
        }
        const float bias = b2[row_base + r];
        #pragma unroll
        for (int b = 0; b < BATCH; ++b) sv[r*8 + b] = acc[b] + bias;
    }
    __syncthreads();

    // pack stage: thread m handles kg pair (2m, 2m+1)
    if (tid < 192) {
        const int kg0 = 2*tid;            // kk-major k index: kk*128 + ci
        const int kk  = kg0 >> 7;
        const int ci0 = kg0 & 127;
        const int r0  = ci0*3 + kk;       // natural w2 row offset
        const int r1  = r0 + 3;
        const int ks  = kg0 >> 4;
        const int kl  = kg0 & 15;
        const int j2      = (kl >> 3) & 1;
        const int lanelow = (kl & 7) >> 1;
        const int co16 = co & 15, cb = co >> 4;
        const int j0       = co16 >> 3;
        const int lanehigh = co16 & 7;
        const int lane = lanehigh*4 + lanelow;
        const int j    = j0 + 2*j2;
        const int e3   = ((ks*8 + cb)*32 + lane)*4 + j;
        #pragma unroll
        for (int b = 0; b < BATCH; ++b)
            g_Wh[(size_t)(b*N_LAYERS + l)*WFULL + e3] =
                pack_bf16x2(sv[r0*8 + b], sv[r1*8 + b]);
    }
}

// =========================================================================
// FUSED 4-layer LVC conv — EXACT round-13 winner (348.8us total).
// Residual in registers; W staged per layer (full buffer) via cp.async,
// next layer's W prefetched during the epilogue.
// =========================================================================
#define SMEM_FUSED ((WFULL + CH*YSTR + 64*XBW) * 4)   /* 231424 B */

__global__ void __launch_bounds__(512, 1)
lvc_fused(const float* __restrict__ x, float* __restrict__ out,
          const float* __restrict__ alpha) {
    extern __shared__ __align__(16) uint32_t smem[];
    uint32_t* sW   = smem;                          // WFULL
    float*    yf32 = (float*)(smem + WFULL);        // 128 x YSTR (staging only)
    uint32_t* xbf  = smem + WFULL + CH*YSTR;        // 64 x XBW

    const int tid  = threadIdx.x;
    const int wid  = tid >> 5;
    const int lane = tid & 31;
    const int wr   = wid & 3;                       // co group (32)
    const int wc   = wid >> 2;                      // t group (40)

    const uint32_t dW = smem_u32(sW);
    const uint32_t dY = smem_u32(yf32);

    for (int g = blockIdx.x; g < BATCH*TILES; g += NCTAS) {
        const int b    = g >> 7;
        const int tile = g & (TILES - 1);
        const int t0   = tile * NT;
        const float* xb = x   + (size_t)b*CH*T_AUDIO;
        float*       ob = out + (size_t)b*CH*T_AUDIO;

        // ---- stage W0 + x chunk [t0-16, t0+144) ----
        {
            const uint32_t* Wg = g_Wh + (size_t)(b*N_LAYERS + 0)*WFULL;
            #pragma unroll
            for (int i = tid; i < WFULL/4; i += 512)
                cp16(dW + i*16, Wg + i*4);
        }
        if (t0 >= 16 && t0 + 144 <= T_AUDIO) {
            #pragma unroll
            for (int idx = tid; idx < CH*40; idx += 512) {
                const int row = idx / 40;
                const int ch  = idx - row*40;
                cp16(dY + (row*YSTR + ch*4)*4,
                     xb + (size_t)row*T_AUDIO + (t0 - 16) + ch*4);
            }
            CP_COMMIT();
            CP_WAIT0();
        } else {
            CP_COMMIT();
            for (int idx = tid; idx < CH*BUFW; idx += 512) {
                const int row = idx / BUFW;
                const int tl  = idx - row*BUFW;
                const int t   = t0 - 16 + tl;
                yf32[row*YSTR + tl] = (t >= 0 && t < T_AUDIO)
                                      ? xb[(size_t)row*T_AUDIO + t] : 0.0f;
            }
            CP_WAIT0();
        }
        __syncthreads();

        // ---- initial pack (x -> bf16x2) + load residual regs ----
        #pragma unroll
        for (int i = tid; i < 64*BUFW; i += 512) {
            const int pr = i / BUFW;
            const int tl = i - pr*BUFW;
            xbf[pr*XBW + 8 + tl] = pack_bf16x2(yf32[(2*pr)*YSTR + tl],
                                               yf32[(2*pr + 1)*YSTR + tl]);
        }
        float res[2][5][4];
        #pragma unroll
        for (int mt = 0; mt < 2; ++mt) {
            #pragma unroll
            for (int n = 0; n < 5; ++n) {
                const int c0 = wc*40 + n*8 + (lane & 3)*2;
                #pragma unroll
                for (int h = 0; h < 2; ++h) {
                    const int cog = wr*32 + mt*16 + (lane >> 2) + h*8;
                    const float2 xv = *(const float2*)&yf32[cog*YSTR + c0];
                    res[mt][n][h*2+0] = xv.x;
                    res[mt][n][h*2+1] = xv.y;
                }
            }
        }
        __syncthreads();

        // ---- 4 layers ----
        #pragma unroll 1
        for (int l = 0; l < N_LAYERS; ++l) {
            const int dil = 1 << l;

            float bias_l[2][2];
            #pragma unroll
            for (int mt = 0; mt < 2; ++mt)
                #pragma unroll
                for (int h = 0; h < 2; ++h)
                    bias_l[mt][h] = g_bias[(b*N_LAYERS + l)*CH
                                           + wr*32 + mt*16 + (lane >> 2) + h*8];

            float acc[2][5][4];
            #pragma unroll
            for (int mt = 0; mt < 2; ++mt)
                #pragma unroll
                for (int n = 0; n < 5; ++n)
                    #pragma unroll
                    for (int q = 0; q < 4; ++q) acc[mt][n][q] = 0.0f;

            #pragma unroll 1
            for (int kk = 0; kk < 3; ++kk) {
                const int off = 8 + (kk - 1)*dil;
                #pragma unroll
                for (int ks8 = 0; ks8 < 8; ++ks8) {
                    const int ks   = kk*8 + ks8;
                    const int row0 = ks8*8 + (lane & 3);
                    const uint32_t* xrow = xbf + row0*XBW + wc*40 + (lane >> 2) + off;
                    uint32_t a[2][4];
                    #pragma unroll
                    for (int mt = 0; mt < 2; ++mt) {
                        const uint4 av = *(const uint4*)(sW + ((ks*8 + wr*2 + mt)*32 + lane)*4);
                        a[mt][0] = av.x; a[mt][1] = av.y; a[mt][2] = av.z; a[mt][3] = av.w;
                    }
                    #pragma unroll
                    for (int n = 0; n < 5; ++n) {
                        uint32_t bf[2];
                        bf[0] = xrow[n*8];
                        bf[1] = xrow[n*8 + 4*XBW];
                        MMA16(acc[0][n], a[0], bf);
                        MMA16(acc[1][n], a[1], bf);
                    }
                }
            }
            __syncthreads();   // all warps done reading sW + xbf

            if (l < 3) {       // prefetch next layer's W (overlaps epilogue)
                const uint32_t* Wg = g_Wh + (size_t)(b*N_LAYERS + l + 1)*WFULL;
                #pragma unroll
                for (int i = tid; i < WFULL/4; i += 512)
                    cp16(dW + i*16, Wg + i*4);
                CP_COMMIT();
            }

            // ---- epilogue: residual in regs; repack xbf or final out ----
            if (l < 3) {
                #pragma unroll
                for (int mt = 0; mt < 2; ++mt) {
                    #pragma unroll
                    for (int n = 0; n < 5; ++n) {
                        const int c0 = wc*40 + n*8 + (lane & 3)*2;
                        #pragma unroll
                        for (int h = 0; h < 2; ++h) {
                            const int cog = wr*32 + mt*16 + (lane >> 2) + h*8;
                            const float y0 = acc[mt][n][h*2+0] + bias_l[mt][h] + res[mt][n][h*2+0];
                            const float y1 = acc[mt][n][h*2+1] + bias_l[mt][h] + res[mt][n][h*2+1];
                            res[mt][n][h*2+0] = y0;
                            res[mt][n][h*2+1] = y1;
                            const float o0 = __shfl_xor_sync(0xffffffffu, y0, 4);
                            const float o1 = __shfl_xor_sync(0xffffffffu, y1, 4);
                            if ((lane & 4) == 0) {
                                uint2 w;
                                w.x = pack_bf16x2(y0, o0);
                                w.y = pack_bf16x2(y1, o1);
                                *(uint2*)&xbf[(cog >> 1)*XBW + 8 + c0] = w;
                            }
                        }
                    }
                }
            } else {
                float al[2][2];
                #pragma unroll
                for (int mt = 0; mt < 2; ++mt)
                    #pragma unroll
                    for (int h = 0; h < 2; ++h)
                        al[mt][h] = alpha[wr*32 + mt*16 + (lane >> 2) + h*8];
                #pragma unroll
                for (int mt = 0; mt < 2; ++mt) {
                    #pragma unroll
                    for (int n = 0; n < 5; ++n) {
                        const int c0 = wc*40 + n*8 + (lane & 3)*2;
                        if (c0 >= 16 && c0 < 144) {
                            #pragma unroll
                            for (int h = 0; h < 2; ++h) {
                                const int cog = wr*32 + mt*16 + (lane >> 2) + h*8;
                                const float y0 = acc[mt][n][h*2+0] + bias_l[mt][h] + res[mt][n][h*2+0];
                                const float y1 = acc[mt][n][h*2+1] + bias_l[mt][h] + res[mt][n][h*2+1];
                                const float a = al[mt][h];
                                const float inva = 1.0f/(a + 1e-8f);
                                const float s0 = sinf(a*y0), s1 = sinf(a*y1);
                                float2 v;
                                v.x = y0 + inva*s0*s0;
                                v.y = y1 + inva*s1*s1;
                                *(float2*)&ob[(size_t)cog*T_AUDIO + t0 + (c0 - 16)] = v;
                            }
                        }
                    }
                }
            }
            if (l < 3) CP_WAIT0();
            __syncthreads();
        }
    }
}

// =========================================================================
extern "C" void kernel_launch(void* const* d_in, const int* in_sizes, int n_in,
                              void* d_out, int out_size) {
    const float* x     = (const float*)d_in[0];
    const float* cond  = (const float*)d_in[1];
    const float* w0    = (const float*)d_in[2];
    const float* b0    = (const float*)d_in[3];
    const float* w1    = (const float*)d_in[4];
    const float* b1    = (const float*)d_in[5];
    const float* w2    = (const float*)d_in[6];
    const float* b2    = (const float*)d_in[7];
    const float* alpha = (const float*)d_in[8];
    float* out = (float*)d_out;

    cond_l0_kernel<<<dim3(8, BATCH), 256>>>(cond, w0, b0);

    const int smemC2 = (64*34 + 64*192) * (int)sizeof(float);
    cudaFuncSetAttribute(cond_l1_kernel, cudaFuncAttributeMaxDynamicSharedMemorySize, smemC2);
    cond_l1_kernel<<<BATCH, 1024, smemC2>>>(w1, b1);

    cudaFuncSetAttribute(weights_kernel, cudaFuncAttributeMaxDynamicSharedMemorySize, SMEM_W);
    weights_kernel<<<512 + (BC + 383)/384, 384, SMEM_W>>>(w2, b2);

    cudaFuncSetAttribute(lvc_fused, cudaFuncAttributeMaxDynamicSharedMemorySize, SMEM_FUSED);
    lvc_fused<<<NCTAS, 512, SMEM_FUSED>>>(x, out, alpha);
}